// round 14
// baseline (speedup 1.0000x reference)
#include <cuda_runtime.h>
#include <cuda_fp16.h>
#include <cstdint>

// ============================================================================
// Collapse (verified): out = 2048 * x @ (Wp@Wv)^T + (2048*Wp@bv + bp)
// fp16 HMMA path, rel_err 4.15e-4 (R12 math — R13's fp16-acc MMA reverted:
// measured rate parity with f32-acc on sm_103, promotion overhead = net loss).
// R14: main GEMM occupancy 2 -> 3 CTAs/SM: 2-stage double buffer (64KB smem),
//   launch_bounds(128,3). Compute per k-tile (32 HMMA/warp ~ 256-500cyc)
//   covers L2-hit latency (~250cyc, operands L2-resident); 12 warps/SM hide
//   sync/wait bubbles. Risk: 166-reg cap (acc 128 + frags 32 + addr).
// ============================================================================

#define KDIM 1024
#define MMAIN 8192
#define NMAIN 1024
#define BK 64

// ---- wc gemm: BM=64, BN=128, single product; stage = A 8KB | B 16KB
#define WBM 64
#define WBN 128
#define WSTAGES 3
#define WSTAGE_BYTES 24576
#define WSMEM_TOTAL (WSTAGES * WSTAGE_BYTES)   // 72 KB
// ---- main gemm: BM=BN=128, 128 threads; 2-stage double buffer
#define MBM 128
#define MBN 128
#define MSTAGES 2
#define MSTAGE_BYTES 32768
#define MSMEM_TOTAL (MSTAGES * MSTAGE_BYTES)   // 64 KB -> 3 CTAs/SM

// -------------------- scratch -------------------------------------------------
__device__ __half g_xh[(size_t)MMAIN * KDIM];
__device__ __half g_wph[(size_t)KDIM * KDIM];
__device__ __half g_wvth[(size_t)KDIM * KDIM];
__device__ __half g_wch[(size_t)KDIM * KDIM];
__device__ float g_bcomb[KDIM];

// -------------------- helpers -------------------------------------------------
__device__ __forceinline__ uint32_t sptr(const void* p) {
    return (uint32_t)__cvta_generic_to_shared(p);
}
__device__ __forceinline__ void cp_async16(uint32_t smem, const void* gmem) {
    asm volatile("cp.async.cg.shared.global [%0], [%1], 16;"
                 :: "r"(smem), "l"(gmem) : "memory");
}
__device__ __forceinline__ void cp_commit() {
    asm volatile("cp.async.commit_group;" ::: "memory");
}
template <int N> __device__ __forceinline__ void cp_wait() {
    asm volatile("cp.async.wait_group %0;" :: "n"(N) : "memory");
}
__device__ __forceinline__ void ldmatrix4(uint32_t* r, uint32_t addr) {
    asm volatile("ldmatrix.sync.aligned.m8n8.x4.shared.b16 {%0,%1,%2,%3}, [%4];"
                 : "=r"(r[0]), "=r"(r[1]), "=r"(r[2]), "=r"(r[3]) : "r"(addr));
}
__device__ __forceinline__ void mma16816(float* c, const uint32_t* a,
                                         uint32_t b0, uint32_t b1) {
    asm volatile(
        "mma.sync.aligned.m16n8k16.row.col.f32.f16.f16.f32 "
        "{%0,%1,%2,%3}, {%4,%5,%6,%7}, {%8,%9}, {%0,%1,%2,%3};"
        : "+f"(c[0]), "+f"(c[1]), "+f"(c[2]), "+f"(c[3])
        : "r"(a[0]), "r"(a[1]), "r"(a[2]), "r"(a[3]), "r"(b0), "r"(b1));
}
__device__ __forceinline__ uint32_t swz(int row, int c) {
    return (uint32_t)(row * 128 + ((c ^ (row & 7)) << 4));
}

// -------------------- fused prep kernel (R12 config) ----------------------------
// grid = 512 blocks x 256 threads:
//   [0, 256)   : Wv transpose -> wvth; 32k x 128n tile, float4 loads, uint4 stores
//   [256, 384) : Wp -> wph (fp16), 2048 float4 per block
//   [384, 512) : bias_combine, 8 rows per block (warp per row)
__global__ __launch_bounds__(256) void prep_kernel(
    const float* __restrict__ Wv, const float* __restrict__ Wp,
    const float* __restrict__ bv, const float* __restrict__ bp,
    __half* __restrict__ wvth, __half* __restrict__ wph)
{
    __shared__ float t[32][133];
    int b = blockIdx.x;
    int tid = threadIdx.x;

    if (b < 256) {
        int bx = (b & 7) * 128;
        int by = (b >> 3) * 32;
#pragma unroll
        for (int i = 0; i < 4; i++) {
            int f4 = tid + i * 256;
            int r = f4 >> 5, c4 = f4 & 31;
            float4 v = *(const float4*)(Wv + (size_t)(by + r) * KDIM + bx + c4 * 4);
            t[r][c4 * 4 + 0] = v.x;
            t[r][c4 * 4 + 1] = v.y;
            t[r][c4 * 4 + 2] = v.z;
            t[r][c4 * 4 + 3] = v.w;
        }
        __syncthreads();
#pragma unroll
        for (int i = 0; i < 2; i++) {
            int task = tid + i * 256;
            int nl = task >> 2;
            int kb = (task & 3) * 8;
            __half2 h[4];
#pragma unroll
            for (int j = 0; j < 4; j++)
                h[j] = __floats2half2_rn(t[kb + 2 * j][nl], t[kb + 2 * j + 1][nl]);
            uint4 pk;
            pk.x = *reinterpret_cast<uint32_t*>(&h[0]);
            pk.y = *reinterpret_cast<uint32_t*>(&h[1]);
            pk.z = *reinterpret_cast<uint32_t*>(&h[2]);
            pk.w = *reinterpret_cast<uint32_t*>(&h[3]);
            *reinterpret_cast<uint4*>(wvth + (size_t)(bx + nl) * KDIM + by + kb) = pk;
        }
    } else if (b < 384) {
        int blk = b - 256;
#pragma unroll
        for (int i = 0; i < 8; i++) {
            size_t idx = (size_t)blk * 2048 + i * 256 + tid;
            float4 v = *(const float4*)(Wp + idx * 4);
            __half2 h0 = __floats2half2_rn(v.x, v.y);
            __half2 h1 = __floats2half2_rn(v.z, v.w);
            uint2 pk;
            pk.x = *reinterpret_cast<uint32_t*>(&h0);
            pk.y = *reinterpret_cast<uint32_t*>(&h1);
            *reinterpret_cast<uint2*>(wph + idx * 4) = pk;
        }
    } else {
        int row = (b - 384) * 8 + (tid >> 5);
        int lane = tid & 31;
        float s = 0.f;
        for (int j = lane * 4; j < KDIM; j += 128) {
            float4 w = *(const float4*)(Wp + (size_t)row * KDIM + j);
            float4 bb = *(const float4*)(bv + j);
            s += w.x * bb.x + w.y * bb.y + w.z * bb.z + w.w * bb.w;
        }
#pragma unroll
        for (int o = 16; o > 0; o >>= 1) s += __shfl_xor_sync(0xffffffff, s, o);
        if (lane == 0) g_bcomb[row] = 2048.0f * s + bp[row];
    }
}

// -------------------- wc GEMM: single fp16 product (+ x conversion) ------------
__global__ __launch_bounds__(256, 1) void wc_gemm_kernel(
    const __half* __restrict__ Ah, const __half* __restrict__ Bh,
    __half* __restrict__ Ch,
    const float* __restrict__ Xsrc, __half* __restrict__ Xdst)
{
    extern __shared__ char smem[];
    const uint32_t sbase = sptr(smem);
    const int tid = threadIdx.x;
    const int wid = tid >> 5, lane = tid & 31;
    const int wm = wid & 1, wn = wid >> 1;
    const int bm = blockIdx.y * WBM, bn = blockIdx.x * WBN;
    const int cta = blockIdx.y * gridDim.x + blockIdx.x;
    const size_t xbase = (size_t)cta * 16384;

    float acc[2][4][4];
#pragma unroll
    for (int i = 0; i < 2; i++)
#pragma unroll
        for (int j = 0; j < 4; j++)
#pragma unroll
            for (int q = 0; q < 4; q++) acc[i][j][q] = 0.f;

    auto load_stage = [&](int t, int s) {
        uint32_t st = sbase + s * WSTAGE_BYTES;
        int kcol = t * BK;
#pragma unroll
        for (int i = 0; i < 2; i++) {
            int chunk = tid + i * 256;
            int r = chunk >> 3, c = chunk & 7;
            cp_async16(st + swz(r, c), Ah + (size_t)(bm + r) * KDIM + kcol + c * 8);
        }
#pragma unroll
        for (int i = 0; i < 4; i++) {
            int chunk = tid + i * 256;
            int r = chunk >> 3, c = chunk & 7;
            cp_async16(st + 8192 + swz(r, c),
                       Bh + (size_t)(bn + r) * KDIM + kcol + c * 8);
        }
    };

    const int NT = KDIM / BK;  // 16
#pragma unroll
    for (int t = 0; t < WSTAGES - 1; t++) { load_stage(t, t); cp_commit(); }

    const int lrow = (lane & 7) + ((lane >> 3) & 1) * 8;
    const int lcol = lane >> 4;

    for (int kt = 0; kt < NT; kt++) {
        cp_wait<WSTAGES - 2>();
        __syncthreads();
        if (kt + WSTAGES - 1 < NT)
            load_stage(kt + WSTAGES - 1, (kt + WSTAGES - 1) % WSTAGES);
        cp_commit();

        float4 xv[4];
        size_t xo = xbase + (size_t)kt * 1024 + tid;
#pragma unroll
        for (int i = 0; i < 4; i++)
            xv[i] = __ldg((const float4*)Xsrc + xo + i * 256);

        uint32_t sa = sbase + (kt % WSTAGES) * WSTAGE_BYTES;
        uint32_t sb = sa + 8192;

#pragma unroll
        for (int s = 0; s < BK / 16; s++) {
            uint32_t ah[2][4], bh[2][4];
#pragma unroll
            for (int im = 0; im < 2; im++)
                ldmatrix4(ah[im], sa + swz(wm * 32 + im * 16 + lrow,
                                           s * 2 + lcol));
#pragma unroll
            for (int jn = 0; jn < 2; jn++)
                ldmatrix4(bh[jn], sb + swz(wn * 32 + jn * 16 + lrow,
                                           s * 2 + lcol));
#pragma unroll
            for (int im = 0; im < 2; im++)
#pragma unroll
                for (int n8 = 0; n8 < 4; n8++) {
                    int jn = n8 >> 1, h = n8 & 1;
                    mma16816(acc[im][n8], ah[im], bh[jn][h], bh[jn][h + 2]);
                }
        }

#pragma unroll
        for (int i = 0; i < 4; i++) {
            __half2 h0 = __floats2half2_rn(xv[i].x, xv[i].y);
            __half2 h1 = __floats2half2_rn(xv[i].z, xv[i].w);
            uint2 pk;
            pk.x = *reinterpret_cast<uint32_t*>(&h0);
            pk.y = *reinterpret_cast<uint32_t*>(&h1);
            *reinterpret_cast<uint2*>(Xdst + (xo + i * 256) * 4) = pk;
        }
    }

    const int qr = lane >> 2, qc = lane & 3;
#pragma unroll
    for (int im = 0; im < 2; im++) {
        int m0 = bm + wm * 32 + im * 16 + qr;
#pragma unroll
        for (int n8 = 0; n8 < 4; n8++) {
            int n0 = bn + wn * 32 + n8 * 8 + qc * 2;
            float* c = acc[im][n8];
#pragma unroll
            for (int q = 0; q < 4; q++) {
                int m = m0 + (q >> 1) * 8;
                int n = n0 + (q & 1);
                Ch[(size_t)m * KDIM + n] = __float2half_rn(c[q]);
            }
        }
    }
}

// -------------------- main GEMM: 128x128 CTA, 4 warps, 2-stage, 3 CTA/SM ------
__global__ __launch_bounds__(128, 3) void main_gemm_kernel(
    const __half* __restrict__ A, const __half* __restrict__ B,
    float* __restrict__ Cout)
{
    extern __shared__ char smem[];
    const uint32_t sbase = sptr(smem);
    const int tid = threadIdx.x;
    const int wid = tid >> 5, lane = tid & 31;
    const int wm = wid & 1;
    const int wn = wid >> 1;
    const int bm = blockIdx.y * MBM, bn = blockIdx.x * MBN;

    float acc[4][8][4];
#pragma unroll
    for (int i = 0; i < 4; i++)
#pragma unroll
        for (int j = 0; j < 8; j++)
#pragma unroll
            for (int q = 0; q < 4; q++) acc[i][j][q] = 0.f;

    auto load_stage = [&](int t, int s) {
        uint32_t sa = sbase + s * MSTAGE_BYTES;
        uint32_t sb = sa + 16384;
        int kcol = t * BK;
#pragma unroll
        for (int i = 0; i < 8; i++) {
            int chunk = tid + i * 128;
            int r = chunk >> 3, c = chunk & 7;
            uint32_t sw = swz(r, c);
            cp_async16(sa + sw, A + (size_t)(bm + r) * KDIM + kcol + c * 8);
            cp_async16(sb + sw, B + (size_t)(bn + r) * KDIM + kcol + c * 8);
        }
    };

    const int NT = KDIM / BK;  // 16
    load_stage(0, 0);
    cp_commit();

    const int lrow = (lane & 7) + ((lane >> 3) & 1) * 8;
    const int lcol = lane >> 4;

    for (int kt = 0; kt < NT; kt++) {
        cp_wait<0>();            // tile kt resident (all outstanding done)
        __syncthreads();         // all warps done reading the other buffer
        if (kt + 1 < NT) {
            load_stage(kt + 1, (kt + 1) % MSTAGES);
            cp_commit();
        }

        uint32_t sa = sbase + (kt % MSTAGES) * MSTAGE_BYTES;
        uint32_t sb = sa + 16384;

#pragma unroll
        for (int s = 0; s < BK / 16; s++) {
            uint32_t af[4][4], bf[4][4];
#pragma unroll
            for (int im = 0; im < 4; im++)
                ldmatrix4(af[im], sa + swz(wm * 64 + im * 16 + lrow,
                                           s * 2 + lcol));
#pragma unroll
            for (int jn = 0; jn < 4; jn++)
                ldmatrix4(bf[jn], sb + swz(wn * 64 + jn * 16 + lrow,
                                           s * 2 + lcol));
#pragma unroll
            for (int im = 0; im < 4; im++)
#pragma unroll
                for (int n8 = 0; n8 < 8; n8++) {
                    int jn = n8 >> 1, h = n8 & 1;
                    mma16816(acc[im][n8], af[im], bf[jn][h], bf[jn][h + 2]);
                }
        }
    }

    const int qr = lane >> 2, qc = lane & 3;
#pragma unroll
    for (int im = 0; im < 4; im++) {
        int m0 = bm + wm * 64 + im * 16 + qr;
#pragma unroll
        for (int n8 = 0; n8 < 8; n8++) {
            int n0 = bn + wn * 64 + n8 * 8 + qc * 2;
            float* c = acc[im][n8];
            float b0 = g_bcomb[n0], b1 = g_bcomb[n0 + 1];
            *(float2*)(Cout + (size_t)m0 * NMAIN + n0) =
                make_float2(2048.f * c[0] + b0, 2048.f * c[1] + b1);
            *(float2*)(Cout + (size_t)(m0 + 8) * NMAIN + n0) =
                make_float2(2048.f * c[2] + b0, 2048.f * c[3] + b1);
        }
    }
}

// -------------------- host ------------------------------------------------------
extern "C" void kernel_launch(void* const* d_in, const int* in_sizes, int n_in,
                              void* d_out, int out_size)
{
    // metadata order: x, Wq, bq, Wk, bk, Wv, bv, Wp, bp
    const float* x  = (const float*)d_in[0];
    const float* Wv = (const float*)d_in[5];
    const float* bv = (const float*)d_in[6];
    const float* Wp = (const float*)d_in[7];
    const float* bp = (const float*)d_in[8];
    float* out = (float*)d_out;

    __half *xh, *wph, *wvth, *wch;
    cudaGetSymbolAddress((void**)&xh, g_xh);
    cudaGetSymbolAddress((void**)&wph, g_wph);
    cudaGetSymbolAddress((void**)&wvth, g_wvth);
    cudaGetSymbolAddress((void**)&wch, g_wch);

    cudaFuncSetAttribute(wc_gemm_kernel,
                         cudaFuncAttributeMaxDynamicSharedMemorySize, WSMEM_TOTAL);
    cudaFuncSetAttribute(main_gemm_kernel,
                         cudaFuncAttributeMaxDynamicSharedMemorySize, MSMEM_TOTAL);

    prep_kernel<<<512, 256>>>(Wv, Wp, bv, bp, wvth, wph);
    wc_gemm_kernel<<<dim3(8, 16), 256, WSMEM_TOTAL>>>(wph, wvth, wch, x, xh);
    main_gemm_kernel<<<dim3(8, 64), 128, MSMEM_TOTAL>>>(xh, wch, out);
}

// round 15
// speedup vs baseline: 1.1043x; 1.1043x over previous
#include <cuda_runtime.h>
#include <cuda_fp16.h>
#include <cstdint>

// ============================================================================
// Collapse (verified): out = 2048 * x @ (Wp@Wv)^T + (2048*Wp@bv + bp)
// fp16 HMMA path, rel_err 4.15e-4.
// R15: prep kernel ELIMINATED. wc GEMM consumes Wp/Wv fp32 directly:
//   - A (Wp): LDG.128 fp32 -> cvt -> swizzled STS fp16 (register double buffer)
//   - B (Wv, [K,N] n-contig): same, stored k-major; fragments via
//     ldmatrix.x4.trans (NN form; b pair = (r[2h], r[2h+1]))
//   - bias_combine folded in as 16 extra CTAs
//   - x conversion kept interleaved in the k-loop
// Main GEMM: R12 config (3-stage cp.async, 128x128, 4 warps, 2 CTA/SM) — at
// its measured mma.sync floor; R13 (fp16-acc) and R14 (2-stage/3CTA) reverted.
// ============================================================================

#define KDIM 1024
#define MMAIN 8192
#define NMAIN 1024
#define BK 64

// ---- wc gemm: BM=64, BN=128; double buffer, stage = A 8KB | B 16KB
#define WBM 64
#define WBN 128
#define WSTAGE_BYTES 24576
#define WSMEM_TOTAL (2 * WSTAGE_BYTES)         // 48 KB
// ---- main gemm: BM=BN=128, 1-product, 128 threads; stage = A|B = 32KB
#define MBM 128
#define MBN 128
#define MSTAGES 3
#define MSTAGE_BYTES 32768
#define MSMEM_TOTAL (MSTAGES * MSTAGE_BYTES)   // 96 KB -> 2 CTAs/SM

// -------------------- scratch -------------------------------------------------
__device__ __half g_xh[(size_t)MMAIN * KDIM];
__device__ __half g_wch[(size_t)KDIM * KDIM];
__device__ float g_bcomb[KDIM];

// -------------------- helpers -------------------------------------------------
__device__ __forceinline__ uint32_t sptr(const void* p) {
    return (uint32_t)__cvta_generic_to_shared(p);
}
__device__ __forceinline__ void cp_async16(uint32_t smem, const void* gmem) {
    asm volatile("cp.async.cg.shared.global [%0], [%1], 16;"
                 :: "r"(smem), "l"(gmem) : "memory");
}
__device__ __forceinline__ void cp_commit() {
    asm volatile("cp.async.commit_group;" ::: "memory");
}
template <int N> __device__ __forceinline__ void cp_wait() {
    asm volatile("cp.async.wait_group %0;" :: "n"(N) : "memory");
}
__device__ __forceinline__ void ldmatrix4(uint32_t* r, uint32_t addr) {
    asm volatile("ldmatrix.sync.aligned.m8n8.x4.shared.b16 {%0,%1,%2,%3}, [%4];"
                 : "=r"(r[0]), "=r"(r[1]), "=r"(r[2]), "=r"(r[3]) : "r"(addr));
}
__device__ __forceinline__ void ldmatrix4t(uint32_t* r, uint32_t addr) {
    asm volatile("ldmatrix.sync.aligned.m8n8.x4.trans.shared.b16 {%0,%1,%2,%3}, [%4];"
                 : "=r"(r[0]), "=r"(r[1]), "=r"(r[2]), "=r"(r[3]) : "r"(addr));
}
__device__ __forceinline__ void mma16816(float* c, const uint32_t* a,
                                         uint32_t b0, uint32_t b1) {
    asm volatile(
        "mma.sync.aligned.m16n8k16.row.col.f32.f16.f16.f32 "
        "{%0,%1,%2,%3}, {%4,%5,%6,%7}, {%8,%9}, {%0,%1,%2,%3};"
        : "+f"(c[0]), "+f"(c[1]), "+f"(c[2]), "+f"(c[3])
        : "r"(a[0]), "r"(a[1]), "r"(a[2]), "r"(a[3]), "r"(b0), "r"(b1));
}
__device__ __forceinline__ uint32_t swz(int row, int c) {
    return (uint32_t)(row * 128 + ((c ^ (row & 7)) << 4));
}
__device__ __forceinline__ uint2 cvt4(float4 v) {
    __half2 h0 = __floats2half2_rn(v.x, v.y);
    __half2 h1 = __floats2half2_rn(v.z, v.w);
    uint2 pk;
    pk.x = *reinterpret_cast<uint32_t*>(&h0);
    pk.y = *reinterpret_cast<uint32_t*>(&h1);
    return pk;
}

// -------------------- wc GEMM (fused: Wc + bias + x conversion) ----------------
// blocks [0,128): Wc = fp16(Wp) @ fp16(Wv), NT math / NN storage:
//   A tile [64m x 64k] from Wp fp32 (k-contig); B tile [64k x 128n] from Wv
//   fp32 (n-contig), stored as two 64x128B swizzled subtiles; B frags via
//   ldmatrix.trans. Register-double-buffered loader, one sync per k-tile.
// blocks [128,144): bcomb[i] = 2048*dot(Wp[i,:],bv) + bp[i].
__global__ __launch_bounds__(256, 1) void wc_fused_kernel(
    const float* __restrict__ Wp, const float* __restrict__ Wv,
    const float* __restrict__ bv, const float* __restrict__ bp,
    __half* __restrict__ Ch,
    const float* __restrict__ Xsrc, __half* __restrict__ Xdst)
{
    const int b = blockIdx.x;
    const int tid = threadIdx.x;

    if (b >= 128) {
        // ---- bias partition: 16 blocks x 64 rows (8 rows per warp) ----
        int warp = tid >> 5, lane = tid & 31;
#pragma unroll 1
        for (int rr = 0; rr < 8; rr++) {
            int row = (b - 128) * 64 + warp * 8 + rr;
            float s = 0.f;
            for (int j = lane * 4; j < KDIM; j += 128) {
                float4 w = *(const float4*)(Wp + (size_t)row * KDIM + j);
                float4 bb = *(const float4*)(bv + j);
                s += w.x * bb.x + w.y * bb.y + w.z * bb.z + w.w * bb.w;
            }
#pragma unroll
            for (int o = 16; o > 0; o >>= 1)
                s += __shfl_xor_sync(0xffffffff, s, o);
            if (lane == 0) g_bcomb[row] = 2048.0f * s + bp[row];
        }
        return;
    }

    // ---- Wc partition ----
    extern __shared__ char smem[];
    const uint32_t sbase = sptr(smem);
    const int wid = tid >> 5, lane = tid & 31;
    const int wm = wid & 1, wn = wid >> 1;
    const int bm = (b >> 3) * WBM;      // Wc row block (16 blocks of 64)
    const int bn = (b & 7) * WBN;       // Wc col block (8 blocks of 128)
    const size_t xbase = (size_t)b * 16384;   // float4 units of x slice

    float acc[2][4][4];
#pragma unroll
    for (int i = 0; i < 2; i++)
#pragma unroll
        for (int j = 0; j < 4; j++)
#pragma unroll
            for (int q = 0; q < 4; q++) acc[i][j][q] = 0.f;

    float4 aReg[4], bReg[8];

    auto ldg_tile = [&](int t) {
        int kcol = t * BK;
#pragma unroll
        for (int i = 0; i < 4; i++) {        // A: 64m x 64k fp32 = 1024 float4
            int f = tid + i * 256;
            int r = f >> 4, c4 = f & 15;
            aReg[i] = *(const float4*)(Wp + (size_t)(bm + r) * KDIM + kcol + c4 * 4);
        }
#pragma unroll
        for (int i = 0; i < 8; i++) {        // B: 64k x 128n fp32 = 2048 float4
            int f = tid + i * 256;
            int kr = f >> 5, nc4 = f & 31;
            bReg[i] = *(const float4*)(Wv + (size_t)(kcol + kr) * KDIM + bn + nc4 * 4);
        }
    };
    auto sts_tile = [&](int s) {
        uint32_t sa = sbase + s * WSTAGE_BYTES;
        uint32_t sb = sa + 8192;
#pragma unroll
        for (int i = 0; i < 4; i++) {
            int f = tid + i * 256;
            int r = f >> 4, c4 = f & 15;
            *reinterpret_cast<uint2*>(
                smem + (sa - sbase) + swz(r, c4 >> 1) + (c4 & 1) * 8) = cvt4(aReg[i]);
        }
#pragma unroll
        for (int i = 0; i < 8; i++) {
            int f = tid + i * 256;
            int kr = f >> 5, nc4 = f & 31;
            uint32_t off = (nc4 >> 4) * 8192 + swz(kr, (nc4 & 15) >> 1) + (nc4 & 1) * 8;
            *reinterpret_cast<uint2*>(smem + (sb - sbase) + off) = cvt4(bReg[i]);
        }
    };

    const int NT = KDIM / BK;  // 16
    const int lrow = (lane & 7) + ((lane >> 3) & 1) * 8;
    const int lcol = lane >> 4;

    ldg_tile(0);

    for (int kt = 0; kt < NT; kt++) {
        sts_tile(kt & 1);
        __syncthreads();
        if (kt + 1 < NT) ldg_tile(kt + 1);   // LDG latency hides under MMAs

        // x conversion LDGs (also hidden under MMAs)
        float4 xv[4];
        size_t xo = xbase + (size_t)kt * 1024 + tid;
#pragma unroll
        for (int i = 0; i < 4; i++)
            xv[i] = __ldg((const float4*)Xsrc + xo + i * 256);

        uint32_t sa = sbase + (kt & 1) * WSTAGE_BYTES;
        uint32_t sb = sa + 8192;

#pragma unroll
        for (int s = 0; s < BK / 16; s++) {
            uint32_t ah[2][4], bt[2][4];
#pragma unroll
            for (int im = 0; im < 2; im++)
                ldmatrix4(ah[im], sa + swz(wm * 32 + im * 16 + lrow,
                                           s * 2 + lcol));
#pragma unroll
            for (int jn = 0; jn < 2; jn++) {
                int nl = wn * 32 + jn * 16 + (lane >> 4) * 8;  // n within tile
                uint32_t off = (nl >> 6) * 8192 + swz(s * 16 + lrow, (nl & 63) >> 3);
                ldmatrix4t(bt[jn], sb + off);
            }
#pragma unroll
            for (int im = 0; im < 2; im++)
#pragma unroll
                for (int n8 = 0; n8 < 4; n8++) {
                    int jn = n8 >> 1, h = n8 & 1;
                    // trans pairing: b0 = k0-7, b1 = k8-15 for n8-half h
                    mma16816(acc[im][n8], ah[im], bt[jn][h * 2], bt[jn][h * 2 + 1]);
                }
        }

#pragma unroll
        for (int i = 0; i < 4; i++)
            *reinterpret_cast<uint2*>(Xdst + (xo + i * 256) * 4) = cvt4(xv[i]);
    }

    const int qr = lane >> 2, qc = lane & 3;
#pragma unroll
    for (int im = 0; im < 2; im++) {
        int m0 = bm + wm * 32 + im * 16 + qr;
#pragma unroll
        for (int n8 = 0; n8 < 4; n8++) {
            int n0 = bn + wn * 32 + n8 * 8 + qc * 2;
            float* c = acc[im][n8];
#pragma unroll
            for (int q = 0; q < 4; q++) {
                int m = m0 + (q >> 1) * 8;
                int n = n0 + (q & 1);
                Ch[(size_t)m * KDIM + n] = __float2half_rn(c[q]);
            }
        }
    }
}

// -------------------- main GEMM: 128x128 CTA, 4 warps of 64x64, 2 CTA/SM ------
__global__ __launch_bounds__(128, 2) void main_gemm_kernel(
    const __half* __restrict__ A, const __half* __restrict__ B,
    float* __restrict__ Cout)
{
    extern __shared__ char smem[];
    const uint32_t sbase = sptr(smem);
    const int tid = threadIdx.x;
    const int wid = tid >> 5, lane = tid & 31;
    const int wm = wid & 1;
    const int wn = wid >> 1;
    const int bm = blockIdx.y * MBM, bn = blockIdx.x * MBN;

    float acc[4][8][4];
#pragma unroll
    for (int i = 0; i < 4; i++)
#pragma unroll
        for (int j = 0; j < 8; j++)
#pragma unroll
            for (int q = 0; q < 4; q++) acc[i][j][q] = 0.f;

    auto load_stage = [&](int t, int s) {
        uint32_t sa = sbase + s * MSTAGE_BYTES;
        uint32_t sb = sa + 16384;
        int kcol = t * BK;
#pragma unroll
        for (int i = 0; i < 8; i++) {
            int chunk = tid + i * 128;
            int r = chunk >> 3, c = chunk & 7;
            uint32_t sw = swz(r, c);
            cp_async16(sa + sw, A + (size_t)(bm + r) * KDIM + kcol + c * 8);
            cp_async16(sb + sw, B + (size_t)(bn + r) * KDIM + kcol + c * 8);
        }
    };

    const int NT = KDIM / BK;  // 16
#pragma unroll
    for (int t = 0; t < MSTAGES - 1; t++) { load_stage(t, t); cp_commit(); }

    const int lrow = (lane & 7) + ((lane >> 3) & 1) * 8;
    const int lcol = lane >> 4;

    for (int kt = 0; kt < NT; kt++) {
        cp_wait<MSTAGES - 2>();
        __syncthreads();
        if (kt + MSTAGES - 1 < NT)
            load_stage(kt + MSTAGES - 1, (kt + MSTAGES - 1) % MSTAGES);
        cp_commit();

        uint32_t sa = sbase + (kt % MSTAGES) * MSTAGE_BYTES;
        uint32_t sb = sa + 16384;

#pragma unroll
        for (int s = 0; s < BK / 16; s++) {
            uint32_t af[4][4], bf[4][4];
#pragma unroll
            for (int im = 0; im < 4; im++)
                ldmatrix4(af[im], sa + swz(wm * 64 + im * 16 + lrow,
                                           s * 2 + lcol));
#pragma unroll
            for (int jn = 0; jn < 4; jn++)
                ldmatrix4(bf[jn], sb + swz(wn * 64 + jn * 16 + lrow,
                                           s * 2 + lcol));
#pragma unroll
            for (int im = 0; im < 4; im++)
#pragma unroll
                for (int n8 = 0; n8 < 8; n8++) {
                    int jn = n8 >> 1, h = n8 & 1;
                    mma16816(acc[im][n8], af[im], bf[jn][h], bf[jn][h + 2]);
                }
        }
    }

    const int qr = lane >> 2, qc = lane & 3;
#pragma unroll
    for (int im = 0; im < 4; im++) {
        int m0 = bm + wm * 64 + im * 16 + qr;
#pragma unroll
        for (int n8 = 0; n8 < 8; n8++) {
            int n0 = bn + wn * 64 + n8 * 8 + qc * 2;
            float* c = acc[im][n8];
            float b0 = g_bcomb[n0], b1 = g_bcomb[n0 + 1];
            *(float2*)(Cout + (size_t)m0 * NMAIN + n0) =
                make_float2(2048.f * c[0] + b0, 2048.f * c[1] + b1);
            *(float2*)(Cout + (size_t)(m0 + 8) * NMAIN + n0) =
                make_float2(2048.f * c[2] + b0, 2048.f * c[3] + b1);
        }
    }
}

// -------------------- host ------------------------------------------------------
extern "C" void kernel_launch(void* const* d_in, const int* in_sizes, int n_in,
                              void* d_out, int out_size)
{
    // metadata order: x, Wq, bq, Wk, bk, Wv, bv, Wp, bp
    const float* x  = (const float*)d_in[0];
    const float* Wv = (const float*)d_in[5];
    const float* bv = (const float*)d_in[6];
    const float* Wp = (const float*)d_in[7];
    const float* bp = (const float*)d_in[8];
    float* out = (float*)d_out;

    __half *xh, *wch;
    cudaGetSymbolAddress((void**)&xh, g_xh);
    cudaGetSymbolAddress((void**)&wch, g_wch);

    cudaFuncSetAttribute(wc_fused_kernel,
                         cudaFuncAttributeMaxDynamicSharedMemorySize, WSMEM_TOTAL);
    cudaFuncSetAttribute(main_gemm_kernel,
                         cudaFuncAttributeMaxDynamicSharedMemorySize, MSMEM_TOTAL);

    wc_fused_kernel<<<144, 256, WSMEM_TOTAL>>>(Wp, Wv, bv, bp, wch, x, xh);
    main_gemm_kernel<<<dim3(8, 64), 128, MSMEM_TOTAL>>>(xh, wch, out);
}